// round 2
// baseline (speedup 1.0000x reference)
#include <cuda_runtime.h>

#define NBATCH 32
#define NSAMP  49152
#define FRAME  2048
#define NFRAME 24
#define NBAND  16
#define TPB    768      // 24 warps; warp w owns frame w
#define TSEG   64       // samples per thread
#define CSTRIDE 12

// A11,A12,A21,A22,C1,C2,E0,E1,E2, pad  per (b,band,frame)
__device__ float g_coef[NBATCH * NBAND * NFRAME * CSTRIDE];
__device__ float g_ig[NBATCH * NFRAME];
__device__ float g_og[NBATCH * NFRAME];

__global__ void coef_kernel(const float* __restrict__ params) {
    int idx = blockIdx.x * blockDim.x + threadIdx.x;
    if (idx < NBATCH * NFRAME) {
        int b = idx / NFRAME, f = idx % NFRAME;
        const float* P = params + b * 50 * NFRAME;
        // BROADBAND (-60,0): db = -60 + 60n ; gain = 10^(db/20) = 10^(3n-3)
        g_ig[idx] = exp10f(3.0f * P[48 * NFRAME + f] - 3.0f);
        g_og[idx] = exp10f(3.0f * P[49 * NFRAME + f] - 3.0f);
    }
    if (idx >= NBATCH * NBAND * NFRAME) return;
    int f    = idx % NFRAME;
    int band = (idx / NFRAME) % NBAND;
    int b    = idx / (NFRAME * NBAND);
    const float* P = params + b * 50 * NFRAME;
    float fn = P[(band * 3 + 0) * NFRAME + f];
    float gn = P[(band * 3 + 1) * NFRAME + f];
    float qn = P[(band * 3 + 2) * NFRAME + f];

    // Q = exp(log 0.5 + qn*(log16 - log0.5))
    double Q = exp(-0.6931471805599453 + (double)qn * 3.4657359027997265);

    double flo, fhi; int type; // 0 hp, 1 lp, 2 lowshelf, 3 highshelf, 4 peak
    if      (band == 0)  { flo = 20.0;   fhi = 500.0;   type = 0; }
    else if (band == 15) { flo = 5000.0; fhi = 20000.0; type = 1; }
    else if (band == 1)  { flo = 50.0;   fhi = 16000.0; type = 2; }
    else if (band == 14) { flo = 50.0;   fhi = 16000.0; type = 3; }
    else                 { flo = 100.0;  fhi = 15000.0; type = 4; }

    double fc = exp(log(flo) + (double)fn * (log(fhi) - log(flo)));
    double g  = tan(3.141592653589793 * fc / 96000.0);
    g = fmin(fmax(g, 1e-6), 100.0);
    double gain = (double)(-24.0f + gn * 48.0f);   // GAIN_RANGE

    double k, a1, a2, a3, m0, m1, m2;
    if (type <= 1) {
        k  = 1.0 / Q;
        a1 = 1.0 / (1.0 + g * (g + k));
        a2 = g * a1; a3 = g * a2;
        if (type == 0) { m0 = 1.0; m1 = -k; m2 = -1.0; }
        else           { m0 = 0.0; m1 = 0.0; m2 = 1.0; }
    } else if (type == 4) { // peak
        double A = exp10(gain / 40.0);
        k  = (gain >= 0.0) ? 1.0 / (Q * A) : A / Q;
        a1 = 1.0 / (1.0 + g * (g + k));
        a2 = g * a1; a3 = g * a2;
        m0 = 1.0; m1 = k * (A * A - 1.0); m2 = 0.0;
    } else {                // shelves
        double A  = exp10(gain / 40.0);
        double sA = sqrt(A);
        k = 1.0 / Q;
        double gs;
        if (type == 2) gs = (gain >= 0.0) ? g / sA : g * sA;
        else           gs = (gain >= 0.0) ? g * sA : g / sA;
        a1 = 1.0 / (1.0 + gs * (gs + k));
        a2 = gs * a1; a3 = gs * a2;
        if (type == 2) { m0 = 1.0;   m1 = k * (A - 1.0);       m2 = A * A - 1.0; }
        else           { m0 = A * A; m1 = k * (1.0 - A) * A;   m2 = 1.0 - A * A; }
    }
    // state transition: s' = M s + c*x ; output y = E0*x + E1*s1 + E2*s2 (pre-update s)
    double t22 = a2 * a2 + a3;
    float* c = &g_coef[idx * CSTRIDE];
    c[0] = (float)(2.0 * a1 - 1.0);          // A11
    c[1] = (float)(-2.0 * a2);               // A12
    c[2] = (float)(2.0 * a1 * a2);           // A21
    c[3] = (float)(1.0 - 2.0 * t22);         // A22
    c[4] = (float)(2.0 * a2);                // C1
    c[5] = (float)(2.0 * t22);               // C2
    c[6] = (float)(m0 + m1 * a2 + m2 * t22); // E0
    c[7] = (float)(a1 * (m1 + m2 * a2));     // E1
    c[8] = (float)(-m1 * a2 + m2 * (1.0 - t22)); // E2
}

// affine compose helper done inline below (mine ∘ theirs, theirs earlier in time)

__global__ __launch_bounds__(TPB, 1) void filter_kernel(
    const float* __restrict__ audio, float* __restrict__ out) {
    extern __shared__ float smem[];
    float* xs       = smem;                        // NSAMP
    float* warpAgg  = smem + NSAMP;                // NFRAME*6
    float* stateIn  = warpAgg + NFRAME * 6;        // NFRAME*2

    const int b    = blockIdx.x;
    const int t    = threadIdx.x;
    const int w    = t >> 5;
    const int lane = t & 31;
    const float* ab = audio + (size_t)b * NSAMP;

    for (int i = t; i < NSAMP; i += TPB)
        xs[i] = ab[i] * g_ig[b * NFRAME + (i >> 11)];
    __syncthreads();

    const int base = t * TSEG;
    for (int band = 0; band < NBAND; band++) {
        const float* cp = &g_coef[((b * NBAND + band) * NFRAME + w) * CSTRIDE];
        const float A11 = cp[0], A12 = cp[1], A21 = cp[2], A22 = cp[3];
        const float C1  = cp[4], C2  = cp[5];
        const float E0  = cp[6], E1  = cp[7], E2  = cp[8];

        // pass 1: segment d-vector (affine applied to zero state)
        float d1 = 0.f, d2 = 0.f;
        #pragma unroll 16
        for (int j = 0; j < TSEG; j++) {
            float xv = xs[base + j];
            float n1 = fmaf(A11, d1, fmaf(A12, d2, C1 * xv));
            float n2 = fmaf(A21, d1, fmaf(A22, d2, C2 * xv));
            d1 = n1; d2 = n2;
        }
        // segment matrix M^64 by repeated squaring
        float P11 = A11, P12 = A12, P21 = A21, P22 = A22;
        #pragma unroll
        for (int sq = 0; sq < 6; sq++) {
            float tr  = P11 + P22;
            float od  = P12 * P21;
            float q11 = fmaf(P11, P11, od);
            float q12 = P12 * tr;
            float q21 = P21 * tr;
            float q22 = fmaf(P22, P22, od);
            P11 = q11; P12 = q12; P21 = q21; P22 = q22;
        }
        // warp inclusive scan of (P,d)
        #pragma unroll
        for (int off = 1; off < 32; off <<= 1) {
            float o11 = __shfl_up_sync(~0u, P11, off);
            float o12 = __shfl_up_sync(~0u, P12, off);
            float o21 = __shfl_up_sync(~0u, P21, off);
            float o22 = __shfl_up_sync(~0u, P22, off);
            float od1 = __shfl_up_sync(~0u, d1,  off);
            float od2 = __shfl_up_sync(~0u, d2,  off);
            if (lane >= off) {
                float n11 = fmaf(P11, o11, P12 * o21);
                float n12 = fmaf(P11, o12, P12 * o22);
                float n21 = fmaf(P21, o11, P22 * o21);
                float n22 = fmaf(P21, o12, P22 * o22);
                float nd1 = fmaf(P11, od1, fmaf(P12, od2, d1));
                float nd2 = fmaf(P21, od1, fmaf(P22, od2, d2));
                P11 = n11; P12 = n12; P21 = n21; P22 = n22; d1 = nd1; d2 = nd2;
            }
        }
        // lane-exclusive prefix from inclusive
        float X11 = __shfl_up_sync(~0u, P11, 1);
        float X12 = __shfl_up_sync(~0u, P12, 1);
        float X21 = __shfl_up_sync(~0u, P21, 1);
        float X22 = __shfl_up_sync(~0u, P22, 1);
        float Xd1 = __shfl_up_sync(~0u, d1, 1);
        float Xd2 = __shfl_up_sync(~0u, d2, 1);
        if (lane == 0) { X11 = 1.f; X12 = 0.f; X21 = 0.f; X22 = 1.f; Xd1 = 0.f; Xd2 = 0.f; }
        if (lane == 31) {
            float* wa = &warpAgg[w * 6];
            wa[0] = P11; wa[1] = P12; wa[2] = P21; wa[3] = P22; wa[4] = d1; wa[5] = d2;
        }
        __syncthreads();

        // block scan of 24 warp aggregates by warp 0 (shfl scan)
        if (t < 32) {
            float q11 = 1.f, q12 = 0.f, q21 = 0.f, q22 = 1.f, qd1 = 0.f, qd2 = 0.f;
            if (lane < NFRAME) {
                const float* wa = &warpAgg[lane * 6];
                q11 = wa[0]; q12 = wa[1]; q21 = wa[2]; q22 = wa[3]; qd1 = wa[4]; qd2 = wa[5];
            }
            #pragma unroll
            for (int off = 1; off < 32; off <<= 1) {
                float o11 = __shfl_up_sync(~0u, q11, off);
                float o12 = __shfl_up_sync(~0u, q12, off);
                float o21 = __shfl_up_sync(~0u, q21, off);
                float o22 = __shfl_up_sync(~0u, q22, off);
                float od1 = __shfl_up_sync(~0u, qd1, off);
                float od2 = __shfl_up_sync(~0u, qd2, off);
                if (lane >= off) {
                    float n11 = fmaf(q11, o11, q12 * o21);
                    float n12 = fmaf(q11, o12, q12 * o22);
                    float n21 = fmaf(q21, o11, q22 * o21);
                    float n22 = fmaf(q21, o12, q22 * o22);
                    float nd1 = fmaf(q11, od1, fmaf(q12, od2, qd1));
                    float nd2 = fmaf(q21, od1, fmaf(q22, od2, qd2));
                    q11 = n11; q12 = n12; q21 = n21; q22 = n22; qd1 = nd1; qd2 = nd2;
                }
            }
            // initial state is zero -> warp-exclusive incoming state = exclusive d
            float ed1 = __shfl_up_sync(~0u, qd1, 1);
            float ed2 = __shfl_up_sync(~0u, qd2, 1);
            if (lane == 0) { ed1 = 0.f; ed2 = 0.f; }
            if (lane < NFRAME) { stateIn[lane * 2] = ed1; stateIn[lane * 2 + 1] = ed2; }
        }
        __syncthreads();

        float sw1 = stateIn[w * 2], sw2 = stateIn[w * 2 + 1];
        float s1 = fmaf(X11, sw1, fmaf(X12, sw2, Xd1));
        float s2 = fmaf(X21, sw1, fmaf(X22, sw2, Xd2));

        // pass 2: replay, emit output in place (own segment only)
        #pragma unroll 16
        for (int j = 0; j < TSEG; j++) {
            float xv = xs[base + j];
            float y  = fmaf(E0, xv, fmaf(E1, s1, E2 * s2));
            float n1 = fmaf(A11, s1, fmaf(A12, s2, C1 * xv));
            float n2 = fmaf(A21, s1, fmaf(A22, s2, C2 * xv));
            xs[base + j] = y;
            s1 = n1; s2 = n2;
        }
        // no barrier needed here: next band's pass 1 reads only this thread's segment
    }
    __syncthreads();
    for (int i = t; i < NSAMP; i += TPB)
        out[(size_t)b * NSAMP + i] = xs[i] * g_og[b * NFRAME + (i >> 11)];
}

extern "C" void kernel_launch(void* const* d_in, const int* in_sizes, int n_in,
                              void* d_out, int out_size) {
    const float* audio  = (const float*)d_in[0];
    const float* params = (const float*)d_in[1];
    if (n_in >= 2 && in_sizes[0] != NBATCH * NSAMP) { // robustness to input order
        const float* tmp = audio; audio = params; params = tmp;
    }
    float* out = (float*)d_out;

    coef_kernel<<<(NBATCH * NBAND * NFRAME + 255) / 256, 256>>>(params);

    size_t smem_bytes = (size_t)(NSAMP + NFRAME * 6 + NFRAME * 2) * sizeof(float);
    cudaFuncSetAttribute(filter_kernel,
                         cudaFuncAttributeMaxDynamicSharedMemorySize,
                         (int)smem_bytes);
    filter_kernel<<<NBATCH, TPB, smem_bytes>>>(audio, out);
}

// round 3
// speedup vs baseline: 2.1549x; 2.1549x over previous
#include <cuda_runtime.h>

#define NBATCH 32
#define NSAMP  49152
#define FRAME  2048
#define NFRAME 24
#define NBAND  16
#define TPB    768      // 24 warps; warp w owns frame w
#define TSEG   64       // samples per thread
#define CSTRIDE 12

// A11,A12,A21,A22,C1,C2,E0,E1,E2, pad  per (b,band,frame)
__device__ float g_coef[NBATCH * NBAND * NFRAME * CSTRIDE];
__device__ float g_ig[NBATCH * NFRAME];
__device__ float g_og[NBATCH * NFRAME];

__global__ void coef_kernel(const float* __restrict__ params) {
    int idx = blockIdx.x * blockDim.x + threadIdx.x;
    if (idx < NBATCH * NFRAME) {
        int b = idx / NFRAME, f = idx % NFRAME;
        const float* P = params + b * 50 * NFRAME;
        // BROADBAND (-60,0): db = -60 + 60n ; gain = 10^(db/20) = 10^(3n-3)
        g_ig[idx] = exp10f(3.0f * P[48 * NFRAME + f] - 3.0f);
        g_og[idx] = exp10f(3.0f * P[49 * NFRAME + f] - 3.0f);
    }
    if (idx >= NBATCH * NBAND * NFRAME) return;
    int f    = idx % NFRAME;
    int band = (idx / NFRAME) % NBAND;
    int b    = idx / (NFRAME * NBAND);
    const float* P = params + b * 50 * NFRAME;
    float fn = P[(band * 3 + 0) * NFRAME + f];
    float gn = P[(band * 3 + 1) * NFRAME + f];
    float qn = P[(band * 3 + 2) * NFRAME + f];

    // Q = exp(log 0.5 + qn*(log16 - log0.5))
    double Q = exp(-0.6931471805599453 + (double)qn * 3.4657359027997265);

    double flo, fhi; int type; // 0 hp, 1 lp, 2 lowshelf, 3 highshelf, 4 peak
    if      (band == 0)  { flo = 20.0;   fhi = 500.0;   type = 0; }
    else if (band == 15) { flo = 5000.0; fhi = 20000.0; type = 1; }
    else if (band == 1)  { flo = 50.0;   fhi = 16000.0; type = 2; }
    else if (band == 14) { flo = 50.0;   fhi = 16000.0; type = 3; }
    else                 { flo = 100.0;  fhi = 15000.0; type = 4; }

    double fc = exp(log(flo) + (double)fn * (log(fhi) - log(flo)));
    double g  = tan(3.141592653589793 * fc / 96000.0);
    g = fmin(fmax(g, 1e-6), 100.0);
    double gain = (double)(-24.0f + gn * 48.0f);   // GAIN_RANGE

    double k, a1, a2, a3, m0, m1, m2;
    if (type <= 1) {
        k  = 1.0 / Q;
        a1 = 1.0 / (1.0 + g * (g + k));
        a2 = g * a1; a3 = g * a2;
        if (type == 0) { m0 = 1.0; m1 = -k; m2 = -1.0; }
        else           { m0 = 0.0; m1 = 0.0; m2 = 1.0; }
    } else if (type == 4) { // peak
        double A = exp10(gain / 40.0);
        k  = (gain >= 0.0) ? 1.0 / (Q * A) : A / Q;
        a1 = 1.0 / (1.0 + g * (g + k));
        a2 = g * a1; a3 = g * a2;
        m0 = 1.0; m1 = k * (A * A - 1.0); m2 = 0.0;
    } else {                // shelves
        double A  = exp10(gain / 40.0);
        double sA = sqrt(A);
        k = 1.0 / Q;
        double gs;
        if (type == 2) gs = (gain >= 0.0) ? g / sA : g * sA;
        else           gs = (gain >= 0.0) ? g * sA : g / sA;
        a1 = 1.0 / (1.0 + gs * (gs + k));
        a2 = gs * a1; a3 = gs * a2;
        if (type == 2) { m0 = 1.0;   m1 = k * (A - 1.0);       m2 = A * A - 1.0; }
        else           { m0 = A * A; m1 = k * (1.0 - A) * A;   m2 = 1.0 - A * A; }
    }
    // state transition: s' = M s + c*x ; output y = E0*x + E1*s1 + E2*s2 (pre-update s)
    double t22 = a2 * a2 + a3;
    float* c = &g_coef[idx * CSTRIDE];
    c[0] = (float)(2.0 * a1 - 1.0);          // A11
    c[1] = (float)(-2.0 * a2);               // A12
    c[2] = (float)(2.0 * a1 * a2);           // A21
    c[3] = (float)(1.0 - 2.0 * t22);         // A22
    c[4] = (float)(2.0 * a2);                // C1
    c[5] = (float)(2.0 * t22);               // C2
    c[6] = (float)(m0 + m1 * a2 + m2 * t22); // E0
    c[7] = (float)(a1 * (m1 + m2 * a2));     // E1
    c[8] = (float)(-m1 * a2 + m2 * (1.0 - t22)); // E2
    c[9] = 0.f; c[10] = 0.f; c[11] = 0.f;
}

// Bank-conflict-free tile addressing: logical (segment o, sample j) lives at
// phys = o*64 + ((j + o) & 63).  At fixed j, bank = (j + lane) & 31 -> all
// 32 lanes of a warp hit distinct banks (the old layout was a 32-way conflict
// on EVERY inner-loop access).
__device__ __forceinline__ int swz(int o, int j) {
    return (o << 6) | ((j + o) & 63);
}

__global__ __launch_bounds__(TPB, 1) void filter_kernel(
    const float* __restrict__ audio, float* __restrict__ out) {
    extern __shared__ float smem[];
    float* xs      = smem;            // NSAMP (swizzled layout)
    float* warpAgg = smem + NSAMP;    // NFRAME*6

    const int b    = blockIdx.x;
    const int t    = threadIdx.x;
    const int w    = t >> 5;
    const int lane = t & 31;
    const float* ab = audio + (size_t)b * NSAMP;

    // coalesced gmem read, conflict-free swizzled smem write
    for (int i = t; i < NSAMP; i += TPB) {
        int o = i >> 6, j = i & 63;
        xs[swz(o, j)] = ab[i] * g_ig[b * NFRAME + (i >> 11)];
    }
    __syncthreads();

    for (int band = 0; band < NBAND; band++) {
        const float4* cp4 = (const float4*)&g_coef[((b * NBAND + band) * NFRAME + w) * CSTRIDE];
        float4 c0 = cp4[0], c1 = cp4[1], c2 = cp4[2];
        const float A11 = c0.x, A12 = c0.y, A21 = c0.z, A22 = c0.w;
        const float C1  = c1.x, C2  = c1.y;
        const float E0  = c1.z, E1  = c1.w, E2 = c2.x;

        // pass 1: segment d-vector (affine applied to zero state)
        float d1 = 0.f, d2 = 0.f;
        #pragma unroll 16
        for (int j = 0; j < TSEG; j++) {
            float xv = xs[swz(t, j)];
            float n1 = fmaf(A11, d1, fmaf(A12, d2, C1 * xv));
            float n2 = fmaf(A21, d1, fmaf(A22, d2, C2 * xv));
            d1 = n1; d2 = n2;
        }
        // segment matrix M^64 by repeated squaring
        float P11 = A11, P12 = A12, P21 = A21, P22 = A22;
        #pragma unroll
        for (int sq = 0; sq < 6; sq++) {
            float tr  = P11 + P22;
            float od  = P12 * P21;
            float q11 = fmaf(P11, P11, od);
            float q12 = P12 * tr;
            float q21 = P21 * tr;
            float q22 = fmaf(P22, P22, od);
            P11 = q11; P12 = q12; P21 = q21; P22 = q22;
        }
        // warp inclusive scan of (P,d)
        #pragma unroll
        for (int off = 1; off < 32; off <<= 1) {
            float o11 = __shfl_up_sync(~0u, P11, off);
            float o12 = __shfl_up_sync(~0u, P12, off);
            float o21 = __shfl_up_sync(~0u, P21, off);
            float o22 = __shfl_up_sync(~0u, P22, off);
            float od1 = __shfl_up_sync(~0u, d1,  off);
            float od2 = __shfl_up_sync(~0u, d2,  off);
            if (lane >= off) {
                float n11 = fmaf(P11, o11, P12 * o21);
                float n12 = fmaf(P11, o12, P12 * o22);
                float n21 = fmaf(P21, o11, P22 * o21);
                float n22 = fmaf(P21, o12, P22 * o22);
                float nd1 = fmaf(P11, od1, fmaf(P12, od2, d1));
                float nd2 = fmaf(P21, od1, fmaf(P22, od2, d2));
                P11 = n11; P12 = n12; P21 = n21; P22 = n22; d1 = nd1; d2 = nd2;
            }
        }
        // lane-exclusive prefix from inclusive
        float X11 = __shfl_up_sync(~0u, P11, 1);
        float X12 = __shfl_up_sync(~0u, P12, 1);
        float X21 = __shfl_up_sync(~0u, P21, 1);
        float X22 = __shfl_up_sync(~0u, P22, 1);
        float Xd1 = __shfl_up_sync(~0u, d1, 1);
        float Xd2 = __shfl_up_sync(~0u, d2, 1);
        if (lane == 0) { X11 = 1.f; X12 = 0.f; X21 = 0.f; X22 = 1.f; Xd1 = 0.f; Xd2 = 0.f; }
        if (lane == 31) {
            float* wa = &warpAgg[w * 6];
            wa[0] = P11; wa[1] = P12; wa[2] = P21; wa[3] = P22; wa[4] = d1; wa[5] = d2;
        }
        __syncthreads();

        // block scan of the 24 warp aggregates: every warp does it redundantly
        // (they'd otherwise idle) -> no second __syncthreads needed.
        float bd1 = 0.f, bd2 = 0.f;
        {
            float q11 = 1.f, q12 = 0.f, q21 = 0.f, q22 = 1.f, qd1 = 0.f, qd2 = 0.f;
            if (lane < NFRAME) {
                const float* wa = &warpAgg[lane * 6];
                q11 = wa[0]; q12 = wa[1]; q21 = wa[2]; q22 = wa[3]; qd1 = wa[4]; qd2 = wa[5];
            }
            #pragma unroll
            for (int off = 1; off < NFRAME; off <<= 1) {
                float o11 = __shfl_up_sync(~0u, q11, off);
                float o12 = __shfl_up_sync(~0u, q12, off);
                float o21 = __shfl_up_sync(~0u, q21, off);
                float o22 = __shfl_up_sync(~0u, q22, off);
                float od1 = __shfl_up_sync(~0u, qd1, off);
                float od2 = __shfl_up_sync(~0u, qd2, off);
                if (lane >= off) {
                    float n11 = fmaf(q11, o11, q12 * o21);
                    float n12 = fmaf(q11, o12, q12 * o22);
                    float n21 = fmaf(q21, o11, q22 * o21);
                    float n22 = fmaf(q21, o12, q22 * o22);
                    float nd1 = fmaf(q11, od1, fmaf(q12, od2, qd1));
                    float nd2 = fmaf(q21, od1, fmaf(q22, od2, qd2));
                    q11 = n11; q12 = n12; q21 = n21; q22 = n22; qd1 = nd1; qd2 = nd2;
                }
            }
            if (w > 0) {  // initial state zero -> warp-incoming state = exclusive d
                bd1 = __shfl_sync(~0u, qd1, w - 1);
                bd2 = __shfl_sync(~0u, qd2, w - 1);
            }
        }

        float s1 = fmaf(X11, bd1, fmaf(X12, bd2, Xd1));
        float s2 = fmaf(X21, bd1, fmaf(X22, bd2, Xd2));

        // pass 2: replay, emit output in place (own segment only)
        #pragma unroll 16
        for (int j = 0; j < TSEG; j++) {
            float xv = xs[swz(t, j)];
            float y  = fmaf(E0, xv, fmaf(E1, s1, E2 * s2));
            float n1 = fmaf(A11, s1, fmaf(A12, s2, C1 * xv));
            float n2 = fmaf(A21, s1, fmaf(A22, s2, C2 * xv));
            xs[swz(t, j)] = y;
            s1 = n1; s2 = n2;
        }
        __syncthreads();  // aggregates reused next band; also orders xs for safety
    }

    for (int i = t; i < NSAMP; i += TPB) {
        int o = i >> 6, j = i & 63;
        out[(size_t)b * NSAMP + i] = xs[swz(o, j)] * g_og[b * NFRAME + (i >> 11)];
    }
}

extern "C" void kernel_launch(void* const* d_in, const int* in_sizes, int n_in,
                              void* d_out, int out_size) {
    const float* audio  = (const float*)d_in[0];
    const float* params = (const float*)d_in[1];
    if (n_in >= 2 && in_sizes[0] != NBATCH * NSAMP) { // robustness to input order
        const float* tmp = audio; audio = params; params = tmp;
    }
    float* out = (float*)d_out;

    coef_kernel<<<(NBATCH * NBAND * NFRAME + 255) / 256, 256>>>(params);

    size_t smem_bytes = (size_t)(NSAMP + NFRAME * 6) * sizeof(float);
    cudaFuncSetAttribute(filter_kernel,
                         cudaFuncAttributeMaxDynamicSharedMemorySize,
                         (int)smem_bytes);
    filter_kernel<<<NBATCH, TPB, smem_bytes>>>(audio, out);
}

// round 7
// speedup vs baseline: 3.0583x; 1.4192x over previous
#include <cuda_runtime.h>

#define NBATCH 32
#define NSAMP  49152
#define FRAME  2048
#define NFRAME 24
#define NBAND  16
#define TPB    384      // 12 warps; thread owns 128 samples = 2 packed segments of 64
#define NW     12
#define TSEG   64       // samples per packed lane
#define ROWF   130      // floats per thread row (128 data + 2 pad; stride 130 => conflict-free LDS.64)
#define CSTRIDE 12

typedef unsigned long long ull;

// A11,A12,A21,A22,C1,C2,E0,E1,E2, pad  per (b,band,frame)
__device__ float g_coef[NBATCH * NBAND * NFRAME * CSTRIDE];
__device__ float g_ig[NBATCH * NFRAME];
__device__ float g_og[NBATCH * NFRAME];

// ---------- packed f32x2 helpers (ptxas will not auto-fuse; PTX-only path) ----------
__device__ __forceinline__ ull pk(float lo, float hi) {
    ull r; asm("mov.b64 %0, {%1, %2};" : "=l"(r) : "f"(lo), "f"(hi)); return r;
}
__device__ __forceinline__ float2 upk(ull v) {
    float2 r; asm("mov.b64 {%0, %1}, %2;" : "=f"(r.x), "=f"(r.y) : "l"(v)); return r;
}
__device__ __forceinline__ ull fma2(ull a, ull b, ull c) {
    ull r; asm("fma.rn.f32x2 %0, %1, %2, %3;" : "=l"(r) : "l"(a), "l"(b), "l"(c)); return r;
}
__device__ __forceinline__ ull mul2(ull a, ull b) {
    ull r; asm("mul.rn.f32x2 %0, %1, %2;" : "=l"(r) : "l"(a), "l"(b)); return r;
}

__global__ void coef_kernel(const float* __restrict__ params) {
    int idx = blockIdx.x * blockDim.x + threadIdx.x;
    if (idx < NBATCH * NFRAME) {
        int b = idx / NFRAME, f = idx % NFRAME;
        const float* P = params + b * 50 * NFRAME;
        // BROADBAND (-60,0): db = -60 + 60n ; gain = 10^(db/20) = 10^(3n-3)
        g_ig[idx] = exp10f(3.0f * P[48 * NFRAME + f] - 3.0f);
        g_og[idx] = exp10f(3.0f * P[49 * NFRAME + f] - 3.0f);
    }
    if (idx >= NBATCH * NBAND * NFRAME) return;
    int f    = idx % NFRAME;
    int band = (idx / NFRAME) % NBAND;
    int b    = idx / (NFRAME * NBAND);
    const float* P = params + b * 50 * NFRAME;
    float fn = P[(band * 3 + 0) * NFRAME + f];
    float gn = P[(band * 3 + 1) * NFRAME + f];
    float qn = P[(band * 3 + 2) * NFRAME + f];

    double Q = exp(-0.6931471805599453 + (double)qn * 3.4657359027997265);

    double flo, fhi; int type; // 0 hp, 1 lp, 2 lowshelf, 3 highshelf, 4 peak
    if      (band == 0)  { flo = 20.0;   fhi = 500.0;   type = 0; }
    else if (band == 15) { flo = 5000.0; fhi = 20000.0; type = 1; }
    else if (band == 1)  { flo = 50.0;   fhi = 16000.0; type = 2; }
    else if (band == 14) { flo = 50.0;   fhi = 16000.0; type = 3; }
    else                 { flo = 100.0;  fhi = 15000.0; type = 4; }

    double fc = exp(log(flo) + (double)fn * (log(fhi) - log(flo)));
    double g  = tan(3.141592653589793 * fc / 96000.0);
    g = fmin(fmax(g, 1e-6), 100.0);
    double gain = (double)(-24.0f + gn * 48.0f);

    double k, a1, a2, a3, m0, m1, m2;
    if (type <= 1) {
        k  = 1.0 / Q;
        a1 = 1.0 / (1.0 + g * (g + k));
        a2 = g * a1; a3 = g * a2;
        if (type == 0) { m0 = 1.0; m1 = -k; m2 = -1.0; }
        else           { m0 = 0.0; m1 = 0.0; m2 = 1.0; }
    } else if (type == 4) { // peak
        double A = exp10(gain / 40.0);
        k  = (gain >= 0.0) ? 1.0 / (Q * A) : A / Q;
        a1 = 1.0 / (1.0 + g * (g + k));
        a2 = g * a1; a3 = g * a2;
        m0 = 1.0; m1 = k * (A * A - 1.0); m2 = 0.0;
    } else {                // shelves
        double A  = exp10(gain / 40.0);
        double sA = sqrt(A);
        k = 1.0 / Q;
        double gs;
        if (type == 2) gs = (gain >= 0.0) ? g / sA : g * sA;
        else           gs = (gain >= 0.0) ? g * sA : g / sA;
        a1 = 1.0 / (1.0 + gs * (gs + k));
        a2 = gs * a1; a3 = gs * a2;
        if (type == 2) { m0 = 1.0;   m1 = k * (A - 1.0);       m2 = A * A - 1.0; }
        else           { m0 = A * A; m1 = k * (1.0 - A) * A;   m2 = 1.0 - A * A; }
    }
    double t22 = a2 * a2 + a3;
    float* c = &g_coef[idx * CSTRIDE];
    c[0] = (float)(2.0 * a1 - 1.0);          // A11
    c[1] = (float)(-2.0 * a2);               // A12
    c[2] = (float)(2.0 * a1 * a2);           // A21
    c[3] = (float)(1.0 - 2.0 * t22);         // A22
    c[4] = (float)(2.0 * a2);                // C1
    c[5] = (float)(2.0 * t22);               // C2
    c[6] = (float)(m0 + m1 * a2 + m2 * t22); // E0
    c[7] = (float)(a1 * (m1 + m2 * a2));     // E1
    c[8] = (float)(-m1 * a2 + m2 * (1.0 - t22)); // E2
    c[9] = 0.f; c[10] = 0.f; c[11] = 0.f;
}

// physical index inside the tile for global sample i:
// thread seg = i>>7 (128 samples/thread), local = i&127, half = local>>6, j = local&63
__device__ __forceinline__ int phys(int i) {
    int seg = i >> 7, loc = i & 127;
    return seg * ROWF + 2 * (loc & 63) + (loc >> 6);
}

__global__ __launch_bounds__(TPB, 1) void filter_kernel(
    const float* __restrict__ audio, float* __restrict__ out) {
    extern __shared__ float smem[];
    float* xs      = smem;                 // TPB*ROWF (interleaved pair layout)
    float* warpAgg = smem + TPB * ROWF;    // [2][NW*6] double-buffered by band parity

    const int b    = blockIdx.x;
    const int t    = threadIdx.x;
    const int w    = t >> 5;
    const int lane = t & 31;
    const float* ab = audio + (size_t)b * NSAMP;

    for (int i = t; i < NSAMP; i += TPB)
        xs[phys(i)] = ab[i] * g_ig[b * NFRAME + (i >> 11)];
    __syncthreads();

    ull* xr = (ull*)(xs + t * ROWF);   // 8B aligned: ROWF*4 = 520 = 8*65

    for (int band = 0; band < NBAND; band++) {
        // thread's frame = (t*128)/2048 = t>>4 ; both packed segments share it
        const float4* cp4 = (const float4*)&g_coef[((b * NBAND + band) * NFRAME + (t >> 4)) * CSTRIDE];
        float4 c0 = cp4[0], c1 = cp4[1], c2 = cp4[2];
        const float A11 = c0.x, A12 = c0.y, A21 = c0.z, A22 = c0.w;
        const float C1  = c1.x, C2  = c1.y;
        const float E0  = c1.z, E1  = c1.w, E2 = c2.x;
        const ull A11p = pk(A11, A11), A12p = pk(A12, A12);
        const ull A21p = pk(A21, A21), A22p = pk(A22, A22);
        const ull C1p  = pk(C1, C1),   C2p  = pk(C2, C2);
        const ull E0p  = pk(E0, E0),   E1p  = pk(E1, E1), E2p = pk(E2, E2);

        // pass 1 (packed over both segments): d-vector from zero state
        ull d1p = 0, d2p = 0;
        #pragma unroll 16
        for (int j = 0; j < TSEG; j++) {
            ull xv = xr[j];
            ull n1 = fma2(A11p, d1p, fma2(A12p, d2p, mul2(C1p, xv)));
            ull n2 = fma2(A21p, d1p, fma2(A22p, d2p, mul2(C2p, xv)));
            d1p = n1; d2p = n2;
        }
        // M^64 (shared by both segments) by 6 squarings
        float P11 = A11, P12 = A12, P21 = A21, P22 = A22;
        #pragma unroll
        for (int sq = 0; sq < 6; sq++) {
            float tr  = P11 + P22;
            float od  = P12 * P21;
            float q11 = fmaf(P11, P11, od);
            float q12 = P12 * tr;
            float q21 = P21 * tr;
            float q22 = fmaf(P22, P22, od);
            P11 = q11; P12 = q12; P21 = q21; P22 = q22;
        }
        // thread-pair aggregate: 128 samples.  T = T_hi o T_lo
        float2 dv1 = upk(d1p), dv2 = upk(d2p);   // .x = lo seg, .y = hi seg
        float G11, G12, G21, G22, gd1, gd2;      // aggregate (M^128, d)
        {
            float tr = P11 + P22, od = P12 * P21;
            G11 = fmaf(P11, P11, od); G12 = P12 * tr;
            G21 = P21 * tr;           G22 = fmaf(P22, P22, od);
            gd1 = fmaf(P11, dv1.x, fmaf(P12, dv2.x, dv1.y));
            gd2 = fmaf(P21, dv1.x, fmaf(P22, dv2.x, dv2.y));
        }
        // warp inclusive scan of thread aggregates
        #pragma unroll
        for (int off = 1; off < 32; off <<= 1) {
            float o11 = __shfl_up_sync(~0u, G11, off);
            float o12 = __shfl_up_sync(~0u, G12, off);
            float o21 = __shfl_up_sync(~0u, G21, off);
            float o22 = __shfl_up_sync(~0u, G22, off);
            float od1 = __shfl_up_sync(~0u, gd1, off);
            float od2 = __shfl_up_sync(~0u, gd2, off);
            if (lane >= off) {
                float n11 = fmaf(G11, o11, G12 * o21);
                float n12 = fmaf(G11, o12, G12 * o22);
                float n21 = fmaf(G21, o11, G22 * o21);
                float n22 = fmaf(G21, o12, G22 * o22);
                float nd1 = fmaf(G11, od1, fmaf(G12, od2, gd1));
                float nd2 = fmaf(G21, od1, fmaf(G22, od2, gd2));
                G11 = n11; G12 = n12; G21 = n21; G22 = n22; gd1 = nd1; gd2 = nd2;
            }
        }
        // lane-exclusive prefix
        float X11 = __shfl_up_sync(~0u, G11, 1);
        float X12 = __shfl_up_sync(~0u, G12, 1);
        float X21 = __shfl_up_sync(~0u, G21, 1);
        float X22 = __shfl_up_sync(~0u, G22, 1);
        float Xd1 = __shfl_up_sync(~0u, gd1, 1);
        float Xd2 = __shfl_up_sync(~0u, gd2, 1);
        if (lane == 0) { X11 = 1.f; X12 = 0.f; X21 = 0.f; X22 = 1.f; Xd1 = 0.f; Xd2 = 0.f; }

        float* wa = warpAgg + (band & 1) * (NW * 6);
        if (lane == 31) {
            float* p = &wa[w * 6];
            p[0] = G11; p[1] = G12; p[2] = G21; p[3] = G22; p[4] = gd1; p[5] = gd2;
        }
        __syncthreads();   // single barrier per band (aggregates double-buffered)

        // block scan of NW warp aggregates, done redundantly per warp
        float bd1 = 0.f, bd2 = 0.f;
        {
            float q11 = 1.f, q12 = 0.f, q21 = 0.f, q22 = 1.f, qd1 = 0.f, qd2 = 0.f;
            if (lane < NW) {
                const float* p = &wa[lane * 6];
                q11 = p[0]; q12 = p[1]; q21 = p[2]; q22 = p[3]; qd1 = p[4]; qd2 = p[5];
            }
            #pragma unroll
            for (int off = 1; off < NW; off <<= 1) {
                float o11 = __shfl_up_sync(~0u, q11, off);
                float o12 = __shfl_up_sync(~0u, q12, off);
                float o21 = __shfl_up_sync(~0u, q21, off);
                float o22 = __shfl_up_sync(~0u, q22, off);
                float od1 = __shfl_up_sync(~0u, qd1, off);
                float od2 = __shfl_up_sync(~0u, qd2, off);
                if (lane >= off) {
                    float n11 = fmaf(q11, o11, q12 * o21);
                    float n12 = fmaf(q11, o12, q12 * o22);
                    float n21 = fmaf(q21, o11, q22 * o21);
                    float n22 = fmaf(q21, o12, q22 * o22);
                    float nd1 = fmaf(q11, od1, fmaf(q12, od2, qd1));
                    float nd2 = fmaf(q21, od1, fmaf(q22, od2, qd2));
                    q11 = n11; q12 = n12; q21 = n21; q22 = n22; qd1 = nd1; qd2 = nd2;
                }
            }
            if (w > 0) {  // zero init state -> warp-incoming = exclusive d
                bd1 = __shfl_sync(~0u, qd1, w - 1);
                bd2 = __shfl_sync(~0u, qd2, w - 1);
            }
        }

        // incoming state of lo segment, then hi segment via M^64 (P) and d_lo
        float sl1 = fmaf(X11, bd1, fmaf(X12, bd2, Xd1));
        float sl2 = fmaf(X21, bd1, fmaf(X22, bd2, Xd2));
        float sh1 = fmaf(P11, sl1, fmaf(P12, sl2, dv1.x));
        float sh2 = fmaf(P21, sl1, fmaf(P22, sl2, dv2.x));
        ull s1p = pk(sl1, sh1), s2p = pk(sl2, sh2);

        // pass 2 (packed): replay, emit in place
        #pragma unroll 16
        for (int j = 0; j < TSEG; j++) {
            ull xv = xr[j];
            ull y  = fma2(E0p, xv, fma2(E1p, s1p, mul2(E2p, s2p)));
            ull n1 = fma2(A11p, s1p, fma2(A12p, s2p, mul2(C1p, xv)));
            ull n2 = fma2(A21p, s1p, fma2(A22p, s2p, mul2(C2p, xv)));
            xr[j] = y;
            s1p = n1; s2p = n2;
        }
        // no trailing barrier: next band's pass 1 reads only this thread's row;
        // warpAgg is double-buffered by band parity.
    }
    __syncthreads();
    for (int i = t; i < NSAMP; i += TPB)
        out[(size_t)b * NSAMP + i] = xs[phys(i)] * g_og[b * NFRAME + (i >> 11)];
}

extern "C" void kernel_launch(void* const* d_in, const int* in_sizes, int n_in,
                              void* d_out, int out_size) {
    const float* audio  = (const float*)d_in[0];
    const float* params = (const float*)d_in[1];
    if (n_in >= 2 && in_sizes[0] != NBATCH * NSAMP) { // robustness to input order
        const float* tmp = audio; audio = params; params = tmp;
    }
    float* out = (float*)d_out;

    coef_kernel<<<(NBATCH * NBAND * NFRAME + 255) / 256, 256>>>(params);

    size_t smem_bytes = (size_t)(TPB * ROWF + 2 * NW * 6) * sizeof(float);
    cudaFuncSetAttribute(filter_kernel,
                         cudaFuncAttributeMaxDynamicSharedMemorySize,
                         (int)smem_bytes);
    filter_kernel<<<NBATCH, TPB, smem_bytes>>>(audio, out);
}

// round 8
// speedup vs baseline: 5.0444x; 1.6494x over previous
#include <cuda_runtime.h>

#define NBATCH 32
#define NSAMP  49152
#define FRAME  2048
#define NFRAME 24
#define NBAND  16
#define CSIZE  4        // CTAs per cluster (one cluster per batch)
#define CSAMP  12288    // samples per CTA
#define CFRAME 6        // frames per CTA
#define TPB    384      // 12 warps
#define NW     12
#define SPT    32       // samples per thread (2 packed halves of 16)
#define HSEG   16       // samples per packed half
#define ROWF   34       // floats per thread row (32 data + 2 pad; 17 x 8B, odd -> conflict-free LDS.64)
#define CSTRIDE 12

typedef unsigned long long ull;

// A11,A12,A21,A22,C1,C2,E0,E1,E2,pad  per (b,band,frame)
__device__ float g_coef[NBATCH * NBAND * NFRAME * CSTRIDE];
__device__ float g_ig[NBATCH * NFRAME];
__device__ float g_og[NBATCH * NFRAME];

// ---------- packed f32x2 helpers ----------
__device__ __forceinline__ ull pk(float lo, float hi) {
    ull r; asm("mov.b64 %0, {%1, %2};" : "=l"(r) : "f"(lo), "f"(hi)); return r;
}
__device__ __forceinline__ float2 upk(ull v) {
    float2 r; asm("mov.b64 {%0, %1}, %2;" : "=f"(r.x), "=f"(r.y) : "l"(v)); return r;
}
__device__ __forceinline__ ull fma2(ull a, ull b, ull c) {
    ull r; asm("fma.rn.f32x2 %0, %1, %2, %3;" : "=l"(r) : "l"(a), "l"(b), "l"(c)); return r;
}
__device__ __forceinline__ ull mul2(ull a, ull b) {
    ull r; asm("mul.rn.f32x2 %0, %1, %2;" : "=l"(r) : "l"(a), "l"(b)); return r;
}

__device__ __forceinline__ unsigned smem_u32(const void* p) {
    unsigned r;
    asm("{ .reg .u64 t; cvta.to.shared.u64 t, %1; cvt.u32.u64 %0, t; }" : "=r"(r) : "l"(p));
    return r;
}

__global__ void coef_kernel(const float* __restrict__ params) {
    int idx = blockIdx.x * blockDim.x + threadIdx.x;
    if (idx < NBATCH * NFRAME) {
        int b = idx / NFRAME, f = idx % NFRAME;
        const float* P = params + b * 50 * NFRAME;
        g_ig[idx] = exp10f(3.0f * P[48 * NFRAME + f] - 3.0f);
        g_og[idx] = exp10f(3.0f * P[49 * NFRAME + f] - 3.0f);
    }
    if (idx >= NBATCH * NBAND * NFRAME) return;
    int f    = idx % NFRAME;
    int band = (idx / NFRAME) % NBAND;
    int b    = idx / (NFRAME * NBAND);
    const float* P = params + b * 50 * NFRAME;
    float fn = P[(band * 3 + 0) * NFRAME + f];
    float gn = P[(band * 3 + 1) * NFRAME + f];
    float qn = P[(band * 3 + 2) * NFRAME + f];

    double Q = exp(-0.6931471805599453 + (double)qn * 3.4657359027997265);

    double flo, fhi; int type; // 0 hp, 1 lp, 2 lowshelf, 3 highshelf, 4 peak
    if      (band == 0)  { flo = 20.0;   fhi = 500.0;   type = 0; }
    else if (band == 15) { flo = 5000.0; fhi = 20000.0; type = 1; }
    else if (band == 1)  { flo = 50.0;   fhi = 16000.0; type = 2; }
    else if (band == 14) { flo = 50.0;   fhi = 16000.0; type = 3; }
    else                 { flo = 100.0;  fhi = 15000.0; type = 4; }

    double fc = exp(log(flo) + (double)fn * (log(fhi) - log(flo)));
    double g  = tan(3.141592653589793 * fc / 96000.0);
    g = fmin(fmax(g, 1e-6), 100.0);
    double gain = (double)(-24.0f + gn * 48.0f);

    double k, a1, a2, a3, m0, m1, m2;
    if (type <= 1) {
        k  = 1.0 / Q;
        a1 = 1.0 / (1.0 + g * (g + k));
        a2 = g * a1; a3 = g * a2;
        if (type == 0) { m0 = 1.0; m1 = -k; m2 = -1.0; }
        else           { m0 = 0.0; m1 = 0.0; m2 = 1.0; }
    } else if (type == 4) { // peak
        double A = exp10(gain / 40.0);
        k  = (gain >= 0.0) ? 1.0 / (Q * A) : A / Q;
        a1 = 1.0 / (1.0 + g * (g + k));
        a2 = g * a1; a3 = g * a2;
        m0 = 1.0; m1 = k * (A * A - 1.0); m2 = 0.0;
    } else {                // shelves
        double A  = exp10(gain / 40.0);
        double sA = sqrt(A);
        k = 1.0 / Q;
        double gs;
        if (type == 2) gs = (gain >= 0.0) ? g / sA : g * sA;
        else           gs = (gain >= 0.0) ? g * sA : g / sA;
        a1 = 1.0 / (1.0 + gs * (gs + k));
        a2 = gs * a1; a3 = gs * a2;
        if (type == 2) { m0 = 1.0;   m1 = k * (A - 1.0);       m2 = A * A - 1.0; }
        else           { m0 = A * A; m1 = k * (1.0 - A) * A;   m2 = 1.0 - A * A; }
    }
    double t22 = a2 * a2 + a3;
    float* c = &g_coef[idx * CSTRIDE];
    c[0] = (float)(2.0 * a1 - 1.0);          // A11
    c[1] = (float)(-2.0 * a2);               // A12
    c[2] = (float)(2.0 * a1 * a2);           // A21
    c[3] = (float)(1.0 - 2.0 * t22);         // A22
    c[4] = (float)(2.0 * a2);                // C1
    c[5] = (float)(2.0 * t22);               // C2
    c[6] = (float)(m0 + m1 * a2 + m2 * t22); // E0
    c[7] = (float)(a1 * (m1 + m2 * a2));     // E1
    c[8] = (float)(-m1 * a2 + m2 * (1.0 - t22)); // E2
    c[9] = 0.f; c[10] = 0.f; c[11] = 0.f;
}

// smem float layout offsets
#define OFF_XS    0
#define OFF_CSM   (TPB * ROWF)                       // 16B-aligned: TPB*ROWF*4 = 52224
#define OFF_WAGG  (OFF_CSM + NBAND * CFRAME * CSTRIDE)
#define OFF_MBOX  (OFF_WAGG + NW * 6)                // [2][6] double-buffered
#define OFF_PEER  (OFF_MBOX + 12)                    // [18]
#define SMEM_FLOATS (OFF_PEER + 18)

// physical index inside tile for CTA-local sample i
__device__ __forceinline__ int phys(int i) {
    int seg = i >> 5, loc = i & 31;
    return seg * ROWF + 2 * (loc & 15) + (loc >> 4);
}

__global__ __launch_bounds__(TPB, 1) __cluster_dims__(CSIZE, 1, 1)
void filter_kernel(const float* __restrict__ audio, float* __restrict__ out) {
    extern __shared__ float smem[];
    float* xs      = smem + OFF_XS;
    float* csm     = smem + OFF_CSM;
    float* warpAgg = smem + OFF_WAGG;
    float* mbox    = smem + OFF_MBOX;
    float* peerAgg = smem + OFF_PEER;

    const int rank = blockIdx.x & (CSIZE - 1);
    const int b    = blockIdx.x >> 2;
    const int t    = threadIdx.x;
    const int w    = t >> 5;
    const int lane = t & 31;
    const int gbase = rank * CSAMP;
    const float* ab = audio + (size_t)b * NSAMP;

    // fill tile (this CTA's quarter), swizzled, coalesced gmem
    for (int i = t; i < CSAMP; i += TPB) {
        int gi = gbase + i;
        xs[phys(i)] = ab[gi] * g_ig[b * NFRAME + (gi >> 11)];
    }
    // preload this CTA's coefficients for all bands into smem
    // (cluster.sync flushes L1 every band; keep coefs resident in smem)
    for (int i = t; i < NBAND * CFRAME * CSTRIDE; i += TPB) {
        int band = i / (CFRAME * CSTRIDE);
        int rem  = i % (CFRAME * CSTRIDE);
        csm[i] = g_coef[((b * NBAND + band) * NFRAME + rank * CFRAME + rem / CSTRIDE) * CSTRIDE
                        + rem % CSTRIDE];
    }
    __syncthreads();

    ull* xr = (ull*)(xs + t * ROWF);   // 8B aligned (ROWF*4 = 136 = 8*17)

    for (int band = 0; band < NBAND; band++) {
        const float4* cp4 = (const float4*)&csm[(band * CFRAME + (t >> 6)) * CSTRIDE];
        float4 c0 = cp4[0], c1 = cp4[1], c2 = cp4[2];
        const float A11 = c0.x, A12 = c0.y, A21 = c0.z, A22 = c0.w;
        const float C1  = c1.x, C2  = c1.y;
        const float E0  = c1.z, E1  = c1.w, E2 = c2.x;
        const ull A11p = pk(A11, A11), A12p = pk(A12, A12);
        const ull A21p = pk(A21, A21), A22p = pk(A22, A22);
        const ull C1p  = pk(C1, C1),   C2p  = pk(C2, C2);
        const ull E0p  = pk(E0, E0),   E1p  = pk(E1, E1), E2p = pk(E2, E2);

        // pass 1 (packed): d-vector from zero state over both 16-sample halves
        ull d1p = 0, d2p = 0;
        #pragma unroll
        for (int j = 0; j < HSEG; j++) {
            ull xv = xr[j];
            ull n1 = fma2(A11p, d1p, fma2(A12p, d2p, mul2(C1p, xv)));
            ull n2 = fma2(A21p, d1p, fma2(A22p, d2p, mul2(C2p, xv)));
            d1p = n1; d2p = n2;
        }
        // M^16 by 4 squarings
        float P11 = A11, P12 = A12, P21 = A21, P22 = A22;
        #pragma unroll
        for (int sq = 0; sq < 4; sq++) {
            float tr  = P11 + P22;
            float od  = P12 * P21;
            float q11 = fmaf(P11, P11, od);
            float q12 = P12 * tr;
            float q21 = P21 * tr;
            float q22 = fmaf(P22, P22, od);
            P11 = q11; P12 = q12; P21 = q21; P22 = q22;
        }
        // thread aggregate over 32 samples: M = P^2, d = P*d_lo + d_hi
        float2 dv1 = upk(d1p), dv2 = upk(d2p);
        float G11, G12, G21, G22, gd1, gd2;
        {
            float tr = P11 + P22, od = P12 * P21;
            G11 = fmaf(P11, P11, od); G12 = P12 * tr;
            G21 = P21 * tr;           G22 = fmaf(P22, P22, od);
            gd1 = fmaf(P11, dv1.x, fmaf(P12, dv2.x, dv1.y));
            gd2 = fmaf(P21, dv1.x, fmaf(P22, dv2.x, dv2.y));
        }
        // warp inclusive scan
        #pragma unroll
        for (int off = 1; off < 32; off <<= 1) {
            float o11 = __shfl_up_sync(~0u, G11, off);
            float o12 = __shfl_up_sync(~0u, G12, off);
            float o21 = __shfl_up_sync(~0u, G21, off);
            float o22 = __shfl_up_sync(~0u, G22, off);
            float od1 = __shfl_up_sync(~0u, gd1, off);
            float od2 = __shfl_up_sync(~0u, gd2, off);
            if (lane >= off) {
                float n11 = fmaf(G11, o11, G12 * o21);
                float n12 = fmaf(G11, o12, G12 * o22);
                float n21 = fmaf(G21, o11, G22 * o21);
                float n22 = fmaf(G21, o12, G22 * o22);
                float nd1 = fmaf(G11, od1, fmaf(G12, od2, gd1));
                float nd2 = fmaf(G21, od1, fmaf(G22, od2, gd2));
                G11 = n11; G12 = n12; G21 = n21; G22 = n22; gd1 = nd1; gd2 = nd2;
            }
        }
        // lane-exclusive prefix (affine of earlier lanes in this warp)
        float X11 = __shfl_up_sync(~0u, G11, 1);
        float X12 = __shfl_up_sync(~0u, G12, 1);
        float X21 = __shfl_up_sync(~0u, G21, 1);
        float X22 = __shfl_up_sync(~0u, G22, 1);
        float Xd1 = __shfl_up_sync(~0u, gd1, 1);
        float Xd2 = __shfl_up_sync(~0u, gd2, 1);
        if (lane == 0) { X11 = 1.f; X12 = 0.f; X21 = 0.f; X22 = 1.f; Xd1 = 0.f; Xd2 = 0.f; }
        if (lane == 31) {
            float* p = &warpAgg[w * 6];
            p[0] = G11; p[1] = G12; p[2] = G21; p[3] = G22; p[4] = gd1; p[5] = gd2;
        }
        __syncthreads();

        // block scan of NW warp aggregates (redundant per warp)
        float q11 = 1.f, q12 = 0.f, q21 = 0.f, q22 = 1.f, qd1 = 0.f, qd2 = 0.f;
        if (lane < NW) {
            const float* p = &warpAgg[lane * 6];
            q11 = p[0]; q12 = p[1]; q21 = p[2]; q22 = p[3]; qd1 = p[4]; qd2 = p[5];
        }
        #pragma unroll
        for (int off = 1; off < NW; off <<= 1) {
            float o11 = __shfl_up_sync(~0u, q11, off);
            float o12 = __shfl_up_sync(~0u, q12, off);
            float o21 = __shfl_up_sync(~0u, q21, off);
            float o22 = __shfl_up_sync(~0u, q22, off);
            float od1 = __shfl_up_sync(~0u, qd1, off);
            float od2 = __shfl_up_sync(~0u, qd2, off);
            if (lane >= off) {
                float n11 = fmaf(q11, o11, q12 * o21);
                float n12 = fmaf(q11, o12, q12 * o22);
                float n21 = fmaf(q21, o11, q22 * o21);
                float n22 = fmaf(q21, o12, q22 * o22);
                float nd1 = fmaf(q11, od1, fmaf(q12, od2, qd1));
                float nd2 = fmaf(q21, od1, fmaf(q22, od2, qd2));
                q11 = n11; q12 = n12; q21 = n21; q22 = n22; qd1 = nd1; qd2 = nd2;
            }
        }
        // warp-exclusive prefix affine (warps 0..w-1) — full M and d now
        float B11 = 1.f, B12 = 0.f, B21 = 0.f, B22 = 1.f, Bd1 = 0.f, Bd2 = 0.f;
        if (w > 0) {
            B11 = __shfl_sync(~0u, q11, w - 1);
            B12 = __shfl_sync(~0u, q12, w - 1);
            B21 = __shfl_sync(~0u, q21, w - 1);
            B22 = __shfl_sync(~0u, q22, w - 1);
            Bd1 = __shfl_sync(~0u, qd1, w - 1);
            Bd2 = __shfl_sync(~0u, qd2, w - 1);
        }
        // CTA total (lane NW-1 of warp 0 holds it) -> mailbox (parity-buffered)
        float* mb = &mbox[(band & 1) * 6];
        if (w == 0 && lane == NW - 1) {
            mb[0] = q11; mb[1] = q12; mb[2] = q21; mb[3] = q22; mb[4] = qd1; mb[5] = qd2;
        }
        // cluster barrier: publishes mailbox (arrive=release, wait=acquire);
        // also acts as a full block barrier.
        asm volatile("barrier.cluster.arrive.aligned;" ::: "memory");
        asm volatile("barrier.cluster.wait.aligned;"   ::: "memory");

        // stage earlier ranks' aggregates from peer DSMEM into local smem
        if (w == 0 && lane < 6 * (CSIZE - 1)) {
            int k = lane / 6, e = lane % 6;
            if (k < rank) {
                unsigned la = smem_u32(&mb[e]);
                unsigned pa;
                asm("mapa.shared::cluster.u32 %0, %1, %2;" : "=r"(pa) : "r"(la), "r"(k));
                float v;
                asm("ld.shared::cluster.f32 %0, [%1];" : "=f"(v) : "r"(pa));
                peerAgg[lane] = v;
            }
        }
        __syncthreads();

        // cluster-incoming state for this CTA (global init state is zero)
        float cs1 = 0.f, cs2 = 0.f;
        #pragma unroll
        for (int k = 0; k < CSIZE - 1; k++) {
            if (k < rank) {
                const float* p = &peerAgg[k * 6];
                float n1 = fmaf(p[0], cs1, fmaf(p[1], cs2, p[4]));
                float n2 = fmaf(p[2], cs1, fmaf(p[3], cs2, p[5]));
                cs1 = n1; cs2 = n2;
            }
        }
        // warp-incoming, lane-incoming, hi-half states
        float ws1 = fmaf(B11, cs1, fmaf(B12, cs2, Bd1));
        float ws2 = fmaf(B21, cs1, fmaf(B22, cs2, Bd2));
        float sl1 = fmaf(X11, ws1, fmaf(X12, ws2, Xd1));
        float sl2 = fmaf(X21, ws1, fmaf(X22, ws2, Xd2));
        float sh1 = fmaf(P11, sl1, fmaf(P12, sl2, dv1.x));
        float sh2 = fmaf(P21, sl1, fmaf(P22, sl2, dv2.x));
        ull s1p = pk(sl1, sh1), s2p = pk(sl2, sh2);

        // pass 2 (packed): replay, emit in place
        #pragma unroll
        for (int j = 0; j < HSEG; j++) {
            ull xv = xr[j];
            ull y  = fma2(E0p, xv, fma2(E1p, s1p, mul2(E2p, s2p)));
            ull n1 = fma2(A11p, s1p, fma2(A12p, s2p, mul2(C1p, xv)));
            ull n2 = fma2(A21p, s1p, fma2(A22p, s2p, mul2(C2p, xv)));
            xr[j] = y;
            s1p = n1; s2p = n2;
        }
        // no trailing block barrier needed: warpAgg's next write is ordered by
        // the cluster barrier (full block barrier) + syncthreads of next band.
    }
    __syncthreads();
    for (int i = t; i < CSAMP; i += TPB) {
        int gi = gbase + i;
        out[(size_t)b * NSAMP + gi] = xs[phys(i)] * g_og[b * NFRAME + (gi >> 11)];
    }
}

extern "C" void kernel_launch(void* const* d_in, const int* in_sizes, int n_in,
                              void* d_out, int out_size) {
    const float* audio  = (const float*)d_in[0];
    const float* params = (const float*)d_in[1];
    if (n_in >= 2 && in_sizes[0] != NBATCH * NSAMP) { // robustness to input order
        const float* tmp = audio; audio = params; params = tmp;
    }
    float* out = (float*)d_out;

    coef_kernel<<<(NBATCH * NBAND * NFRAME + 255) / 256, 256>>>(params);

    size_t smem_bytes = (size_t)SMEM_FLOATS * sizeof(float);
    cudaFuncSetAttribute(filter_kernel,
                         cudaFuncAttributeMaxDynamicSharedMemorySize,
                         (int)smem_bytes);
    filter_kernel<<<NBATCH * CSIZE, TPB, smem_bytes>>>(audio, out);
}

// round 11
// speedup vs baseline: 5.9937x; 1.1882x over previous
#include <cuda_runtime.h>

#define NBATCH 32
#define NSAMP  49152
#define FRAME  2048
#define NFRAME 24
#define NBAND  16
#define CSIZE  4        // CTAs per cluster (one cluster per batch)
#define CSAMP  12288    // samples per CTA
#define CFRAME 6        // frames per CTA
#define TPB    384      // 12 warps
#define NW     12
#define HSEG   16       // samples per packed half (thread owns 32 samples)
#define ROWF   34       // floats per thread row (32 data + 2 pad; odd 8B count -> conflict-free LDS.64)
#define CSTRIDE 12

typedef unsigned long long ull;

// ---------- packed f32x2 helpers ----------
__device__ __forceinline__ ull pk(float lo, float hi) {
    ull r; asm("mov.b64 %0, {%1, %2};" : "=l"(r) : "f"(lo), "f"(hi)); return r;
}
__device__ __forceinline__ float2 upk(ull v) {
    float2 r; asm("mov.b64 {%0, %1}, %2;" : "=f"(r.x), "=f"(r.y) : "l"(v)); return r;
}
__device__ __forceinline__ ull fma2(ull a, ull b, ull c) {
    ull r; asm("fma.rn.f32x2 %0, %1, %2, %3;" : "=l"(r) : "l"(a), "l"(b), "l"(c)); return r;
}
__device__ __forceinline__ ull mul2(ull a, ull b) {
    ull r; asm("mul.rn.f32x2 %0, %1, %2;" : "=l"(r) : "l"(a), "l"(b)); return r;
}
__device__ __forceinline__ unsigned smem_u32(const void* p) {
    unsigned r;
    asm("{ .reg .u64 t; cvta.to.shared.u64 t, %1; cvt.u32.u64 %0, t; }" : "=r"(r) : "l"(p));
    return r;
}

// smem float layout offsets
#define OFF_XS    0
#define OFF_CSM   (TPB * ROWF)                       // 16B-aligned: TPB*ROWF*4 = 52224
#define OFF_WAGG  (OFF_CSM + NBAND * CFRAME * CSTRIDE)
#define OFF_MBOX  (OFF_WAGG + NW * 6)                // [2][6] double-buffered
#define OFF_PEER  (OFF_MBOX + 12)                    // [18]
#define OFF_IG    (OFF_PEER + 18)                    // [6]
#define OFF_OG    (OFF_IG + 6)                       // [6]
#define SMEM_FLOATS (OFF_OG + 6)

// physical index inside tile for CTA-local sample i
__device__ __forceinline__ int phys(int i) {
    int seg = i >> 5, loc = i & 31;
    return seg * ROWF + 2 * (loc & 15) + (loc >> 4);
}

__global__ __launch_bounds__(TPB, 1) __cluster_dims__(CSIZE, 1, 1)
void filter_kernel(const float* __restrict__ audio,
                   const float* __restrict__ params,
                   float* __restrict__ out) {
    extern __shared__ float smem[];
    float* xs      = smem + OFF_XS;
    float* csm     = smem + OFF_CSM;
    float* warpAgg = smem + OFF_WAGG;
    float* mbox    = smem + OFF_MBOX;
    float* peerAgg = smem + OFF_PEER;
    float* ig_s    = smem + OFF_IG;
    float* og_s    = smem + OFF_OG;

    const int rank = blockIdx.x & (CSIZE - 1);
    const int b    = blockIdx.x >> 2;
    const int t    = threadIdx.x;
    const int w    = t >> 5;
    const int lane = t & 31;
    const int gbase = rank * CSAMP;
    const float* ab = audio + (size_t)b * NSAMP;
    const float* P  = params + (size_t)b * 50 * NFRAME;

    // --- broadband gains for this CTA's 6 frames (needed by fill) ---
    if (t < CFRAME) {
        int f = rank * CFRAME + t;
        // BROADBAND (-60,0): gain = 10^(3n-3)
        ig_s[t] = exp10f(3.0f * P[48 * NFRAME + f] - 3.0f);
        og_s[t] = exp10f(3.0f * P[49 * NFRAME + f] - 3.0f);
    }
    __syncthreads();

    // --- coefficient computation (threads 0..95; fp64, once) overlapped with
    //     tile fill (all threads; DRAM-latency bound) ---
    if (t < NBAND * CFRAME) {
        int band = t / CFRAME;
        int f    = rank * CFRAME + (t % CFRAME);
        float fn = P[(band * 3 + 0) * NFRAME + f];
        float gn = P[(band * 3 + 1) * NFRAME + f];
        float qn = P[(band * 3 + 2) * NFRAME + f];

        double Q = exp(-0.6931471805599453 + (double)qn * 3.4657359027997265);

        double flo, fhi; int type; // 0 hp, 1 lp, 2 lowshelf, 3 highshelf, 4 peak
        if      (band == 0)  { flo = 20.0;   fhi = 500.0;   type = 0; }
        else if (band == 15) { flo = 5000.0; fhi = 20000.0; type = 1; }
        else if (band == 1)  { flo = 50.0;   fhi = 16000.0; type = 2; }
        else if (band == 14) { flo = 50.0;   fhi = 16000.0; type = 3; }
        else                 { flo = 100.0;  fhi = 15000.0; type = 4; }

        double fc = exp(log(flo) + (double)fn * (log(fhi) - log(flo)));
        double g  = tan(3.141592653589793 * fc / 96000.0);
        g = fmin(fmax(g, 1e-6), 100.0);
        double gain = (double)(-24.0f + gn * 48.0f);

        double k, a1, a2, a3, m0, m1, m2;
        if (type <= 1) {
            k  = 1.0 / Q;
            a1 = 1.0 / (1.0 + g * (g + k));
            a2 = g * a1; a3 = g * a2;
            if (type == 0) { m0 = 1.0; m1 = -k; m2 = -1.0; }
            else           { m0 = 0.0; m1 = 0.0; m2 = 1.0; }
        } else if (type == 4) { // peak
            double A = exp10(gain / 40.0);
            k  = (gain >= 0.0) ? 1.0 / (Q * A) : A / Q;
            a1 = 1.0 / (1.0 + g * (g + k));
            a2 = g * a1; a3 = g * a2;
            m0 = 1.0; m1 = k * (A * A - 1.0); m2 = 0.0;
        } else {                // shelves
            double A  = exp10(gain / 40.0);
            double sA = sqrt(A);
            k = 1.0 / Q;
            double gs;
            if (type == 2) gs = (gain >= 0.0) ? g / sA : g * sA;
            else           gs = (gain >= 0.0) ? g * sA : g / sA;
            a1 = 1.0 / (1.0 + gs * (gs + k));
            a2 = gs * a1; a3 = gs * a2;
            if (type == 2) { m0 = 1.0;   m1 = k * (A - 1.0);       m2 = A * A - 1.0; }
            else           { m0 = A * A; m1 = k * (1.0 - A) * A;   m2 = 1.0 - A * A; }
        }
        double t22 = a2 * a2 + a3;
        float* c = &csm[t * CSTRIDE];
        c[0] = (float)(2.0 * a1 - 1.0);          // A11
        c[1] = (float)(-2.0 * a2);               // A12
        c[2] = (float)(2.0 * a1 * a2);           // A21
        c[3] = (float)(1.0 - 2.0 * t22);         // A22
        c[4] = (float)(2.0 * a2);                // C1
        c[5] = (float)(2.0 * t22);               // C2
        c[6] = (float)(m0 + m1 * a2 + m2 * t22); // E0
        c[7] = (float)(a1 * (m1 + m2 * a2));     // E1
        c[8] = (float)(-m1 * a2 + m2 * (1.0 - t22)); // E2
        c[9] = 0.f; c[10] = 0.f; c[11] = 0.f;
    }

    // fill tile (this CTA's quarter), swizzled, coalesced gmem
    for (int i = t; i < CSAMP; i += TPB)
        xs[phys(i)] = ab[gbase + i] * ig_s[i >> 11];
    __syncthreads();

    ull* xr = (ull*)(xs + t * ROWF);   // 8B aligned (ROWF*4 = 136 = 8*17)

    for (int band = 0; band < NBAND; band++) {
        const float4* cp4 = (const float4*)&csm[(band * CFRAME + (t >> 6)) * CSTRIDE];
        float4 c0 = cp4[0], c1 = cp4[1], c2 = cp4[2];
        const float A11 = c0.x, A12 = c0.y, A21 = c0.z, A22 = c0.w;
        const float C1  = c1.x, C2  = c1.y;
        const float E0  = c1.z, E1  = c1.w, E2 = c2.x;
        const ull A11p = pk(A11, A11), A12p = pk(A12, A12);
        const ull A21p = pk(A21, A21), A22p = pk(A22, A22);
        const ull C1p  = pk(C1, C1),   C2p  = pk(C2, C2);
        const ull E0p  = pk(E0, E0),   E1p  = pk(E1, E1), E2p = pk(E2, E2);

        // pass 1 (packed): d-vector from zero state over both 16-sample halves
        ull d1p = 0, d2p = 0;
        #pragma unroll
        for (int j = 0; j < HSEG; j++) {
            ull xv = xr[j];
            ull n1 = fma2(A11p, d1p, fma2(A12p, d2p, mul2(C1p, xv)));
            ull n2 = fma2(A21p, d1p, fma2(A22p, d2p, mul2(C2p, xv)));
            d1p = n1; d2p = n2;
        }
        // M^16 by 4 squarings
        float P11 = A11, P12 = A12, P21 = A21, P22 = A22;
        #pragma unroll
        for (int sq = 0; sq < 4; sq++) {
            float tr  = P11 + P22;
            float od  = P12 * P21;
            float q11 = fmaf(P11, P11, od);
            float q12 = P12 * tr;
            float q21 = P21 * tr;
            float q22 = fmaf(P22, P22, od);
            P11 = q11; P12 = q12; P21 = q21; P22 = q22;
        }
        // thread aggregate over 32 samples: M = P^2, d = P*d_lo + d_hi
        float2 dv1 = upk(d1p), dv2 = upk(d2p);
        float G11, G12, G21, G22, gd1, gd2;
        {
            float tr = P11 + P22, od = P12 * P21;
            G11 = fmaf(P11, P11, od); G12 = P12 * tr;
            G21 = P21 * tr;           G22 = fmaf(P22, P22, od);
            gd1 = fmaf(P11, dv1.x, fmaf(P12, dv2.x, dv1.y));
            gd2 = fmaf(P21, dv1.x, fmaf(P22, dv2.x, dv2.y));
        }
        // warp inclusive scan
        #pragma unroll
        for (int off = 1; off < 32; off <<= 1) {
            float o11 = __shfl_up_sync(~0u, G11, off);
            float o12 = __shfl_up_sync(~0u, G12, off);
            float o21 = __shfl_up_sync(~0u, G21, off);
            float o22 = __shfl_up_sync(~0u, G22, off);
            float od1 = __shfl_up_sync(~0u, gd1, off);
            float od2 = __shfl_up_sync(~0u, gd2, off);
            if (lane >= off) {
                float n11 = fmaf(G11, o11, G12 * o21);
                float n12 = fmaf(G11, o12, G12 * o22);
                float n21 = fmaf(G21, o11, G22 * o21);
                float n22 = fmaf(G21, o12, G22 * o22);
                float nd1 = fmaf(G11, od1, fmaf(G12, od2, gd1));
                float nd2 = fmaf(G21, od1, fmaf(G22, od2, gd2));
                G11 = n11; G12 = n12; G21 = n21; G22 = n22; gd1 = nd1; gd2 = nd2;
            }
        }
        // lane-exclusive prefix
        float X11 = __shfl_up_sync(~0u, G11, 1);
        float X12 = __shfl_up_sync(~0u, G12, 1);
        float X21 = __shfl_up_sync(~0u, G21, 1);
        float X22 = __shfl_up_sync(~0u, G22, 1);
        float Xd1 = __shfl_up_sync(~0u, gd1, 1);
        float Xd2 = __shfl_up_sync(~0u, gd2, 1);
        if (lane == 0) { X11 = 1.f; X12 = 0.f; X21 = 0.f; X22 = 1.f; Xd1 = 0.f; Xd2 = 0.f; }
        if (lane == 31) {
            float* p = &warpAgg[w * 6];
            p[0] = G11; p[1] = G12; p[2] = G21; p[3] = G22; p[4] = gd1; p[5] = gd2;
        }
        __syncthreads();

        // block scan of NW warp aggregates (redundant per warp)
        float q11 = 1.f, q12 = 0.f, q21 = 0.f, q22 = 1.f, qd1 = 0.f, qd2 = 0.f;
        if (lane < NW) {
            const float* p = &warpAgg[lane * 6];
            q11 = p[0]; q12 = p[1]; q21 = p[2]; q22 = p[3]; qd1 = p[4]; qd2 = p[5];
        }
        #pragma unroll
        for (int off = 1; off < NW; off <<= 1) {
            float o11 = __shfl_up_sync(~0u, q11, off);
            float o12 = __shfl_up_sync(~0u, q12, off);
            float o21 = __shfl_up_sync(~0u, q21, off);
            float o22 = __shfl_up_sync(~0u, q22, off);
            float od1 = __shfl_up_sync(~0u, qd1, off);
            float od2 = __shfl_up_sync(~0u, qd2, off);
            if (lane >= off) {
                float n11 = fmaf(q11, o11, q12 * o21);
                float n12 = fmaf(q11, o12, q12 * o22);
                float n21 = fmaf(q21, o11, q22 * o21);
                float n22 = fmaf(q21, o12, q22 * o22);
                float nd1 = fmaf(q11, od1, fmaf(q12, od2, qd1));
                float nd2 = fmaf(q21, od1, fmaf(q22, od2, qd2));
                q11 = n11; q12 = n12; q21 = n21; q22 = n22; qd1 = nd1; qd2 = nd2;
            }
        }
        // warp-exclusive prefix affine (warps 0..w-1)
        float B11 = 1.f, B12 = 0.f, B21 = 0.f, B22 = 1.f, Bd1 = 0.f, Bd2 = 0.f;
        if (w > 0) {
            B11 = __shfl_sync(~0u, q11, w - 1);
            B12 = __shfl_sync(~0u, q12, w - 1);
            B21 = __shfl_sync(~0u, q21, w - 1);
            B22 = __shfl_sync(~0u, q22, w - 1);
            Bd1 = __shfl_sync(~0u, qd1, w - 1);
            Bd2 = __shfl_sync(~0u, qd2, w - 1);
        }
        // CTA total (lane NW-1 of warp 0 holds it) -> mailbox (parity-buffered)
        float* mb = &mbox[(band & 1) * 6];
        if (w == 0 && lane == NW - 1) {
            mb[0] = q11; mb[1] = q12; mb[2] = q21; mb[3] = q22; mb[4] = qd1; mb[5] = qd2;
        }
        // cluster barrier: publishes mailbox (arrive=release, wait=acquire);
        // also acts as a full block barrier.
        asm volatile("barrier.cluster.arrive.aligned;" ::: "memory");
        asm volatile("barrier.cluster.wait.aligned;"   ::: "memory");

        // stage earlier ranks' aggregates from peer DSMEM into local smem
        if (w == 0 && lane < 6 * (CSIZE - 1)) {
            int k = lane / 6, e = lane % 6;
            if (k < rank) {
                unsigned la = smem_u32(&mb[e]);
                unsigned pa;
                asm("mapa.shared::cluster.u32 %0, %1, %2;" : "=r"(pa) : "r"(la), "r"(k));
                float v;
                asm("ld.shared::cluster.f32 %0, [%1];" : "=f"(v) : "r"(pa));
                peerAgg[lane] = v;
            }
        }
        __syncthreads();

        // cluster-incoming state for this CTA (global init state is zero)
        float cs1 = 0.f, cs2 = 0.f;
        #pragma unroll
        for (int k = 0; k < CSIZE - 1; k++) {
            if (k < rank) {
                const float* p = &peerAgg[k * 6];
                float n1 = fmaf(p[0], cs1, fmaf(p[1], cs2, p[4]));
                float n2 = fmaf(p[2], cs1, fmaf(p[3], cs2, p[5]));
                cs1 = n1; cs2 = n2;
            }
        }
        // warp-incoming, lane-incoming, hi-half states
        float ws1 = fmaf(B11, cs1, fmaf(B12, cs2, Bd1));
        float ws2 = fmaf(B21, cs1, fmaf(B22, cs2, Bd2));
        float sl1 = fmaf(X11, ws1, fmaf(X12, ws2, Xd1));
        float sl2 = fmaf(X21, ws1, fmaf(X22, ws2, Xd2));
        float sh1 = fmaf(P11, sl1, fmaf(P12, sl2, dv1.x));
        float sh2 = fmaf(P21, sl1, fmaf(P22, sl2, dv2.x));
        ull s1p = pk(sl1, sh1), s2p = pk(sl2, sh2);

        // pass 2 (packed): replay, emit in place
        #pragma unroll
        for (int j = 0; j < HSEG; j++) {
            ull xv = xr[j];
            ull y  = fma2(E0p, xv, fma2(E1p, s1p, mul2(E2p, s2p)));
            ull n1 = fma2(A11p, s1p, fma2(A12p, s2p, mul2(C1p, xv)));
            ull n2 = fma2(A21p, s1p, fma2(A22p, s2p, mul2(C2p, xv)));
            xr[j] = y;
            s1p = n1; s2p = n2;
        }
    }
    __syncthreads();
    for (int i = t; i < CSAMP; i += TPB) {
        int gi = gbase + i;
        out[(size_t)b * NSAMP + gi] = xs[phys(i)] * og_s[i >> 11];
    }
}

extern "C" void kernel_launch(void* const* d_in, const int* in_sizes, int n_in,
                              void* d_out, int out_size) {
    const float* audio  = (const float*)d_in[0];
    const float* params = (const float*)d_in[1];
    if (n_in >= 2 && in_sizes[0] != NBATCH * NSAMP) { // robustness to input order
        const float* tmp = audio; audio = params; params = tmp;
    }
    float* out = (float*)d_out;

    size_t smem_bytes = (size_t)SMEM_FLOATS * sizeof(float);
    cudaFuncSetAttribute(filter_kernel,
                         cudaFuncAttributeMaxDynamicSharedMemorySize,
                         (int)smem_bytes);
    filter_kernel<<<NBATCH * CSIZE, TPB, smem_bytes>>>(audio, params, out);
}